// round 15
// baseline (speedup 1.0000x reference)
#include <cuda_runtime.h>
#include <cstdint>

// Problem shape (static per reference): N=2048, L=512, D=256, B=256
#define N_PROT 2048
#define L_SEQ  512
#define D_DIM  256
#define B_SEG  256

// Three-level tail taper (R12/R13 each confirmed the drain-tail model):
//   region A: proteins [0, 1792)     full CTAs       (512 rows, weight 16)
//   region B: proteins [1792, 2016)  quarter-CTAs    (128 rows, weight 4)
//   region C: proteins [2016, 2044)  eighth-CTAs     ( 64 rows, weight 2)
//   region D: proteins [2044, 2048)  sixteenth-CTAs  ( 32 rows, weight 1)
// High block-ids are issued last by the HW distributor, so B,C,D land in
// the end-of-grid drain window with geometrically finer work quanta.
#define A_PROT   1792
#define B_PROT   224
#define C_PROT   28
#define D_PROT   4
#define B_BASE   A_PROT                     // 1792
#define C_BASE   (B_BASE + B_PROT)          // 2016
#define D_BASE   (C_BASE + C_PROT)          // 2044
#define GRID_A   A_PROT                     // 1792
#define GRID_B   (B_PROT * 4)               // 896
#define GRID_C   (C_PROT * 8)               // 224
#define GRID_D   (D_PROT * 16)              // 64
#define GRID     (GRID_A + GRID_B + GRID_C + GRID_D)   // 2976
#define W_TOTAL  16                         // sixteenth-units per protein

// Scratch (__device__ globals zero-initialized at module load; finalizer
// restores them to zero each launch — invariant across graph replays).
__device__ float g_acc[B_SEG * D_DIM];   // segment sums (16B-aligned rows)
__device__ int   g_done[B_SEG];          // sixteenth-units arrived per segment

// Dtype-robust key fetch. keys buffer is either int32[2048] or int64[2048].
// Sorted keys in [0,256) with every segment non-empty => last key == 255.
//   int32 layout: word[2047] == 255
//   int64 layout: word[2047] == high word of element 1023 == 0
__device__ __forceinline__ int load_key(const int* k32, bool is32, int n) {
    int key = is32 ? __ldg(&k32[n]) : __ldg(&k32[2 * n]);
    return min(max(key, 0), B_SEG - 1);   // never form a wild address
}

// 256 threads: thread t owns float4-column (t&63), row-phase t>>6.
// Inner loop: 8 independent LDG.128 per thread (MLP=8, measured sweet
// spot; MLP=16 flat — per-warp LDG queue full at 8). __launch_bounds__
// (256,4) = 64-reg budget keeps all 8 loads live. __ldcs streaming loads.
// A 32-row D-slice still runs one full 8-load batch per thread (rows
// r0+4k, k=0..7), so the per-CTA BW ramp is preserved at every level.
// g_done counts sixteenth-units; the finalizer (last-slice CTA of the
// last protein of its sorted segment) spin-waits for proteins*16.
__global__ __launch_bounds__(256, 4) void pool_fused_kernel(
    const float* __restrict__ embeds,    // [N, L, D] fp32
    const int* __restrict__ keys_raw,    // int32 view of batch_keys
    float* __restrict__ out              // [B, D] fp32
) {
    const int bid = blockIdx.x;
    const int t = threadIdx.x;

    // block -> (protein n, row range, signal weight, finalizer-eligible)
    int n, row_beg, row_end, weight;
    bool last_slice;
    if (bid < GRID_A) {
        n = bid;  row_beg = 0;  row_end = L_SEQ;
        weight = 16;  last_slice = true;
    } else if (bid < GRID_A + GRID_B) {
        const int q = bid - GRID_A;
        n = B_BASE + (q >> 2);
        const int s = q & 3;
        row_beg = s * 128;  row_end = row_beg + 128;
        weight = 4;  last_slice = (s == 3);
    } else if (bid < GRID_A + GRID_B + GRID_C) {
        const int q = bid - (GRID_A + GRID_B);
        n = C_BASE + (q >> 3);
        const int s = q & 7;
        row_beg = s * 64;  row_end = row_beg + 64;
        weight = 2;  last_slice = (s == 7);
    } else {
        const int q = bid - (GRID_A + GRID_B + GRID_C);
        n = D_BASE + (q >> 4);
        const int s = q & 15;
        row_beg = s * 32;  row_end = row_beg + 32;
        weight = 1;  last_slice = (s == 15);
    }

    const bool is32 = (__ldg(&keys_raw[N_PROT - 1]) == (B_SEG - 1));
    const int key = load_key(keys_raw, is32, n);
    const bool seg_end =
        (n == N_PROT - 1) || (load_key(keys_raw, is32, n + 1) != key);
    const bool is_finalizer = seg_end && last_slice;

    // ---- streaming partial sum (at the LTS chip cap, ~7.0 TB/s) ----
    const float4* __restrict__ row =
        (const float4*)(embeds + (size_t)n * (L_SEQ * D_DIM));
    const int c  = t & 63;   // float4 column (0..63)
    const int r0 = t >> 6;   // row-phase (0..3)

    float4 acc0 = make_float4(0.f, 0.f, 0.f, 0.f);
    float4 acc1 = make_float4(0.f, 0.f, 0.f, 0.f);
    float4 acc2 = make_float4(0.f, 0.f, 0.f, 0.f);
    float4 acc3 = make_float4(0.f, 0.f, 0.f, 0.f);
    // rows visited: row_beg+r0, +4, ...; batch 8 per outer iter (stride 32).
    for (int l = row_beg + r0; l < row_end; l += 32) {
        float4 v0 = __ldcs(&row[(l +  0) * (D_DIM / 4) + c]);
        float4 v1 = __ldcs(&row[(l +  4) * (D_DIM / 4) + c]);
        float4 v2 = __ldcs(&row[(l +  8) * (D_DIM / 4) + c]);
        float4 v3 = __ldcs(&row[(l + 12) * (D_DIM / 4) + c]);
        float4 v4 = __ldcs(&row[(l + 16) * (D_DIM / 4) + c]);
        float4 v5 = __ldcs(&row[(l + 20) * (D_DIM / 4) + c]);
        float4 v6 = __ldcs(&row[(l + 24) * (D_DIM / 4) + c]);
        float4 v7 = __ldcs(&row[(l + 28) * (D_DIM / 4) + c]);
        acc0.x += v0.x; acc0.y += v0.y; acc0.z += v0.z; acc0.w += v0.w;
        acc1.x += v1.x; acc1.y += v1.y; acc1.z += v1.z; acc1.w += v1.w;
        acc2.x += v2.x; acc2.y += v2.y; acc2.z += v2.z; acc2.w += v2.w;
        acc3.x += v3.x; acc3.y += v3.y; acc3.z += v3.z; acc3.w += v3.w;
        acc0.x += v4.x; acc0.y += v4.y; acc0.z += v4.z; acc0.w += v4.w;
        acc1.x += v5.x; acc1.y += v5.y; acc1.z += v5.z; acc1.w += v5.w;
        acc2.x += v6.x; acc2.y += v6.y; acc2.z += v6.z; acc2.w += v6.w;
        acc3.x += v7.x; acc3.y += v7.y; acc3.z += v7.z; acc3.w += v7.w;
    }
    float4 acc = make_float4(acc0.x + acc1.x + acc2.x + acc3.x,
                             acc0.y + acc1.y + acc2.y + acc3.y,
                             acc0.z + acc1.z + acc2.z + acc3.z,
                             acc0.w + acc1.w + acc2.w + acc3.w);

    __shared__ float4 sdata[256];
    sdata[t] = acc;
    __syncthreads();

    if (t < 64) {
        float4 a = sdata[t];
        float4 b = sdata[t + 64];
        float4 e = sdata[t + 128];
        float4 f = sdata[t + 192];
        float4 r = make_float4(a.x + b.x + e.x + f.x,
                               a.y + b.y + e.y + f.y,
                               a.z + b.z + e.z + f.z,
                               a.w + b.w + e.w + f.w);
        // single 16B vector atomic (sm_90+): 1 LTS lane-op instead of 4
        float4* dst = (float4*)(g_acc + key * D_DIM + t * 4);
        atomicAdd(dst, r);
        __threadfence();   // release: my g_acc atomic visible before signal
    }
    __syncthreads();

    if (t == 0) atomicAdd(&g_done[key], weight);

    if (!is_finalizer) return;

    // ---- finalizer (one CTA per segment; only it binary-searches) ----
    __shared__ int s_count;
    if (t == 0) {
        // first index of this segment in the sorted keys
        int lo = 0, hi = n;
        while (lo < hi) {
            int mid = (lo + hi) >> 1;
            if (load_key(keys_raw, is32, mid) < key) lo = mid + 1;
            else hi = mid;
        }
        const int count = (n - lo + 1) * W_TOTAL;  // sixteenth-units
        // acquire: wait for all peers' signals (HW-sleep on the L2 line)
        while (atomicAdd(&g_done[key], 0) < count) __nanosleep(64);
        __threadfence();
        g_done[key] = 0;                   // reset for next replay
        s_count = count;                   // = proteins * 16
    }
    __syncthreads();

    const float inv = (float)W_TOTAL / ((float)s_count * (float)L_SEQ);
    const int i = key * D_DIM + t;         // one column per thread
    const float sum = __ldcg(&g_acc[i]);   // L2-coherent after acquire fence
    out[i] = sum * inv;
    g_acc[i] = 0.0f;                       // reset for next replay
}

extern "C" void kernel_launch(void* const* d_in, const int* in_sizes, int n_in,
                              void* d_out, int out_size) {
    const float* embeds = (const float*)d_in[0];
    const int*   keys   = (const int*)d_in[1];   // int32 view; dtype detected in-kernel
    float*       out    = (float*)d_out;

    pool_fused_kernel<<<GRID, 256>>>(embeds, keys, out);
}

// round 16
// speedup vs baseline: 1.0015x; 1.0015x over previous
#include <cuda_runtime.h>
#include <cstdint>

// Problem shape (static per reference): N=2048, L=512, D=256, B=256
#define N_PROT 2048
#define L_SEQ  512
#define D_DIM  256
#define B_SEG  256

// Two-level tail taper (best measured config, R13 = 152.10us):
//   region A: proteins [0, 1792)     full CTAs    (512 rows, weight 8)
//   region B: proteins [1792, 2016)  quarter-CTAs (128 rows, weight 2)
//   region C: proteins [2016, 2048)  eighth-CTAs  ( 64 rows, weight 1)
// High block-ids are issued last by the HW distributor, so B then C land
// in the end-of-grid drain window with finer work quanta. A third taper
// level (R14) measured flat — taper is exhausted at this granularity.
#define A_PROT   1792
#define B_PROT   224
#define C_PROT   32
#define B_BASE   A_PROT                    // 1792
#define C_BASE   (A_PROT + B_PROT)         // 2016
#define GRID_A   A_PROT                    // 1792
#define GRID_B   (B_PROT * 4)              // 896
#define GRID_C   (C_PROT * 8)              // 256
#define GRID     (GRID_A + GRID_B + GRID_C)   // 2944
#define W_TOTAL  8                         // eighth-units per protein

// Scratch (__device__ globals zero-initialized at module load; finalizer
// restores them to zero each launch — invariant across graph replays).
__device__ float g_acc[B_SEG * D_DIM];   // segment sums (16B-aligned rows)
__device__ int   g_done[B_SEG];          // eighth-units arrived per segment

// Dtype-robust key fetch. keys buffer is either int32[2048] or int64[2048].
// Sorted keys in [0,256) with every segment non-empty => last key == 255.
//   int32 layout: word[2047] == 255
//   int64 layout: word[2047] == high word of element 1023 == 0
__device__ __forceinline__ int load_key(const int* k32, bool is32, int n) {
    int key = is32 ? __ldg(&k32[n]) : __ldg(&k32[2 * n]);
    return min(max(key, 0), B_SEG - 1);   // never form a wild address
}

// 256 threads: thread t owns float4-column (t&63), row-phase t>>6.
// Inner loop: 8 independent LDG.128 per thread (MLP=8, measured sweet
// spot; MLP=16 flat — per-warp LDG queue full at 8). __launch_bounds__
// (256,4) = 64-reg budget keeps all 8 loads live. __ldcs streaming loads
// (zero-reuse 1 GiB stream). g_done counts eighth-units: full CTA signals
// 8, quarter 2, eighth 1; the finalizer (last-slice CTA of the last
// protein of its sorted segment) spin-waits for proteins*8, then divides,
// writes out, and resets scratch for the next graph replay.
__global__ __launch_bounds__(256, 4) void pool_fused_kernel(
    const float* __restrict__ embeds,    // [N, L, D] fp32
    const int* __restrict__ keys_raw,    // int32 view of batch_keys
    float* __restrict__ out              // [B, D] fp32
) {
    const int bid = blockIdx.x;
    const int t = threadIdx.x;

    // block -> (protein n, row range, signal weight, finalizer-eligible)
    int n, row_beg, row_end, weight;
    bool last_slice;
    if (bid < GRID_A) {
        n = bid;  row_beg = 0;  row_end = L_SEQ;
        weight = 8;  last_slice = true;
    } else if (bid < GRID_A + GRID_B) {
        const int q = bid - GRID_A;
        n = B_BASE + (q >> 2);
        const int s = q & 3;
        row_beg = s * 128;  row_end = row_beg + 128;
        weight = 2;  last_slice = (s == 3);
    } else {
        const int q = bid - (GRID_A + GRID_B);
        n = C_BASE + (q >> 3);
        const int s = q & 7;
        row_beg = s * 64;  row_end = row_beg + 64;
        weight = 1;  last_slice = (s == 7);
    }

    const bool is32 = (__ldg(&keys_raw[N_PROT - 1]) == (B_SEG - 1));
    const int key = load_key(keys_raw, is32, n);
    const bool seg_end =
        (n == N_PROT - 1) || (load_key(keys_raw, is32, n + 1) != key);
    const bool is_finalizer = seg_end && last_slice;

    // ---- streaming partial sum (~7.0 TB/s, ~88% of HBM spec) ----
    const float4* __restrict__ row =
        (const float4*)(embeds + (size_t)n * (L_SEQ * D_DIM));
    const int c  = t & 63;   // float4 column (0..63)
    const int r0 = t >> 6;   // row-phase (0..3)

    float4 acc0 = make_float4(0.f, 0.f, 0.f, 0.f);
    float4 acc1 = make_float4(0.f, 0.f, 0.f, 0.f);
    float4 acc2 = make_float4(0.f, 0.f, 0.f, 0.f);
    float4 acc3 = make_float4(0.f, 0.f, 0.f, 0.f);
    // rows visited: row_beg+r0, +4, ...; batch 8 per outer iter (stride 32).
    for (int l = row_beg + r0; l < row_end; l += 32) {
        float4 v0 = __ldcs(&row[(l +  0) * (D_DIM / 4) + c]);
        float4 v1 = __ldcs(&row[(l +  4) * (D_DIM / 4) + c]);
        float4 v2 = __ldcs(&row[(l +  8) * (D_DIM / 4) + c]);
        float4 v3 = __ldcs(&row[(l + 12) * (D_DIM / 4) + c]);
        float4 v4 = __ldcs(&row[(l + 16) * (D_DIM / 4) + c]);
        float4 v5 = __ldcs(&row[(l + 20) * (D_DIM / 4) + c]);
        float4 v6 = __ldcs(&row[(l + 24) * (D_DIM / 4) + c]);
        float4 v7 = __ldcs(&row[(l + 28) * (D_DIM / 4) + c]);
        acc0.x += v0.x; acc0.y += v0.y; acc0.z += v0.z; acc0.w += v0.w;
        acc1.x += v1.x; acc1.y += v1.y; acc1.z += v1.z; acc1.w += v1.w;
        acc2.x += v2.x; acc2.y += v2.y; acc2.z += v2.z; acc2.w += v2.w;
        acc3.x += v3.x; acc3.y += v3.y; acc3.z += v3.z; acc3.w += v3.w;
        acc0.x += v4.x; acc0.y += v4.y; acc0.z += v4.z; acc0.w += v4.w;
        acc1.x += v5.x; acc1.y += v5.y; acc1.z += v5.z; acc1.w += v5.w;
        acc2.x += v6.x; acc2.y += v6.y; acc2.z += v6.z; acc2.w += v6.w;
        acc3.x += v7.x; acc3.y += v7.y; acc3.z += v7.z; acc3.w += v7.w;
    }
    float4 acc = make_float4(acc0.x + acc1.x + acc2.x + acc3.x,
                             acc0.y + acc1.y + acc2.y + acc3.y,
                             acc0.z + acc1.z + acc2.z + acc3.z,
                             acc0.w + acc1.w + acc2.w + acc3.w);

    __shared__ float4 sdata[256];
    sdata[t] = acc;
    __syncthreads();

    if (t < 64) {
        float4 a = sdata[t];
        float4 b = sdata[t + 64];
        float4 e = sdata[t + 128];
        float4 f = sdata[t + 192];
        float4 r = make_float4(a.x + b.x + e.x + f.x,
                               a.y + b.y + e.y + f.y,
                               a.z + b.z + e.z + f.z,
                               a.w + b.w + e.w + f.w);
        // single 16B vector atomic (sm_90+): 1 LTS lane-op instead of 4
        float4* dst = (float4*)(g_acc + key * D_DIM + t * 4);
        atomicAdd(dst, r);
        __threadfence();   // release: my g_acc atomic visible before signal
    }
    __syncthreads();

    if (t == 0) atomicAdd(&g_done[key], weight);

    if (!is_finalizer) return;

    // ---- finalizer (one CTA per segment; only it binary-searches) ----
    __shared__ int s_count;
    if (t == 0) {
        // first index of this segment in the sorted keys
        int lo = 0, hi = n;
        while (lo < hi) {
            int mid = (lo + hi) >> 1;
            if (load_key(keys_raw, is32, mid) < key) lo = mid + 1;
            else hi = mid;
        }
        const int count = (n - lo + 1) * W_TOTAL;  // eighth-units expected
        // acquire: wait for all peers' signals (HW-sleep on the L2 line)
        while (atomicAdd(&g_done[key], 0) < count) __nanosleep(64);
        __threadfence();
        g_done[key] = 0;                   // reset for next replay
        s_count = count;                   // = proteins * 8
    }
    __syncthreads();

    const float inv = (float)W_TOTAL / ((float)s_count * (float)L_SEQ);
    const int i = key * D_DIM + t;         // one column per thread
    const float sum = __ldcg(&g_acc[i]);   // L2-coherent after acquire fence
    out[i] = sum * inv;
    g_acc[i] = 0.0f;                       // reset for next replay
}

extern "C" void kernel_launch(void* const* d_in, const int* in_sizes, int n_in,
                              void* d_out, int out_size) {
    const float* embeds = (const float*)d_in[0];
    const int*   keys   = (const int*)d_in[1];   // int32 view; dtype detected in-kernel
    float*       out    = (float*)d_out;

    pool_fused_kernel<<<GRID, 256>>>(embeds, keys, out);
}